// round 6
// baseline (speedup 1.0000x reference)
#include <cuda_runtime.h>

// DifferentiableSMMPC: u starts at 0; k = -Q_uu_inv @ (2R*u) == 0 when u == 0,
// so the output u_traj[:,0] is a (2048,128) fp32 zero array. Pure 1 MiB zero
// store, launch-ramp bound. Minimal footprint: 16 CTAs x 256 threads, each
// thread zeroing 256 B via 8x 256-bit stores (one base reg + imm offsets).

__global__ void __launch_bounds__(256) smmpc_zero_fill_v8x8(float* __restrict__ out) {
    // 4096 threads; chunk c (32 B) written by thread (c % 4096) -> coalesced.
    unsigned t = blockIdx.x * 256u + threadIdx.x;          // 0..4095
    float* p = out + (unsigned long long)t * 8u;
    const float z = 0.0f;
    // stride between a thread's chunks = 4096 chunks * 32 B = 131072 B
    asm volatile(
        "st.global.v8.f32 [%0+0],       {%1,%1,%1,%1,%1,%1,%1,%1};\n\t"
        "st.global.v8.f32 [%0+131072],  {%1,%1,%1,%1,%1,%1,%1,%1};\n\t"
        "st.global.v8.f32 [%0+262144],  {%1,%1,%1,%1,%1,%1,%1,%1};\n\t"
        "st.global.v8.f32 [%0+393216],  {%1,%1,%1,%1,%1,%1,%1,%1};\n\t"
        "st.global.v8.f32 [%0+524288],  {%1,%1,%1,%1,%1,%1,%1,%1};\n\t"
        "st.global.v8.f32 [%0+655360],  {%1,%1,%1,%1,%1,%1,%1,%1};\n\t"
        "st.global.v8.f32 [%0+786432],  {%1,%1,%1,%1,%1,%1,%1,%1};\n\t"
        "st.global.v8.f32 [%0+917504],  {%1,%1,%1,%1,%1,%1,%1,%1};\n\t"
        :: "l"(p), "f"(z) : "memory");
}

// Guarded generic fallback (any out_size).
__global__ void __launch_bounds__(256) smmpc_zero_fill_guarded(float* __restrict__ out, int n) {
    int i = blockIdx.x * blockDim.x + threadIdx.x;
    if (i < n) out[i] = 0.0f;
}

extern "C" void kernel_launch(void* const* d_in, const int* in_sizes, int n_in,
                              void* d_out, int out_size) {
    (void)d_in; (void)in_sizes; (void)n_in;
    // Expected out_size = 2048*128 = 262144 fp32 = 1 MiB.
    if (out_size == 262144) {
        smmpc_zero_fill_v8x8<<<16, 256>>>(reinterpret_cast<float*>(d_out));
    } else {
        int threads = 256;
        int blocks = (out_size + threads - 1) / threads;
        smmpc_zero_fill_guarded<<<blocks, threads>>>(reinterpret_cast<float*>(d_out), out_size);
    }
}

// round 7
// speedup vs baseline: 1.3684x; 1.3684x over previous
#include <cuda_runtime.h>

// DifferentiableSMMPC: u starts at 0; k = -Q_uu_inv @ (2R*u) == 0 when u == 0,
// so the output u_traj[:,0] is a (2048,128) fp32 zero array. Pure 1 MiB zero
// store, launch-ramp bound. Optimum found empirically: one wide store per
// thread (no serial chains), moderate thread count, CTAs spread over SMs.
// 128 CTAs x 256 threads = 32768 threads, each one 32 B st.global.v8.f32.

__global__ void __launch_bounds__(256) smmpc_zero_fill_v8x1(float* __restrict__ out) {
    unsigned t = blockIdx.x * 256u + threadIdx.x;      // 0..32767
    float* p = out + (unsigned long long)t * 8u;       // 32 B per thread, coalesced
    asm volatile(
        "st.global.v8.f32 [%0], {%1,%1,%1,%1,%1,%1,%1,%1};\n\t"
        :: "l"(p), "f"(0.0f) : "memory");
}

// Guarded generic fallback (any out_size).
__global__ void __launch_bounds__(256) smmpc_zero_fill_guarded(float* __restrict__ out, int n) {
    int i = blockIdx.x * blockDim.x + threadIdx.x;
    if (i < n) out[i] = 0.0f;
}

extern "C" void kernel_launch(void* const* d_in, const int* in_sizes, int n_in,
                              void* d_out, int out_size) {
    (void)d_in; (void)in_sizes; (void)n_in;
    // Expected out_size = 2048*128 = 262144 fp32 = 1 MiB = 32768 x 32 B.
    if (out_size == 262144) {
        smmpc_zero_fill_v8x1<<<128, 256>>>(reinterpret_cast<float*>(d_out));
    } else {
        int threads = 256;
        int blocks = (out_size + threads - 1) / threads;
        smmpc_zero_fill_guarded<<<blocks, threads>>>(reinterpret_cast<float*>(d_out), out_size);
    }
}

// round 8
// speedup vs baseline: 1.4444x; 1.0556x over previous
#include <cuda_runtime.h>

// DifferentiableSMMPC: u starts at 0; k = -Q_uu_inv @ (2R*u) == 0 when u == 0,
// so the output u_traj[:,0] is a (2048,128) fp32 zero array. Pure 1 MiB zero
// store, launch/replay-floor bound (kernel ~3.4-3.8us regardless of config).
// Best measured config: 64 CTAs x 256 threads, 2x 256-bit stores per thread.
// Second store uses an immediate offset (+512 KiB) off the same base register
// to avoid a second 64-bit address computation.

__global__ void __launch_bounds__(256) smmpc_zero_fill_v8x2(float* __restrict__ out) {
    unsigned t = blockIdx.x * 256u + threadIdx.x;      // 0..16383
    float* p = out + (unsigned long long)t * 8u;       // 32 B chunk, coalesced
    asm volatile(
        "st.global.v8.f32 [%0],        {%1,%1,%1,%1,%1,%1,%1,%1};\n\t"
        "st.global.v8.f32 [%0+524288], {%1,%1,%1,%1,%1,%1,%1,%1};\n\t"
        :: "l"(p), "f"(0.0f) : "memory");
}

// Guarded generic fallback (any out_size).
__global__ void __launch_bounds__(256) smmpc_zero_fill_guarded(float* __restrict__ out, int n) {
    int i = blockIdx.x * blockDim.x + threadIdx.x;
    if (i < n) out[i] = 0.0f;
}

extern "C" void kernel_launch(void* const* d_in, const int* in_sizes, int n_in,
                              void* d_out, int out_size) {
    (void)d_in; (void)in_sizes; (void)n_in;
    // Expected out_size = 2048*128 = 262144 fp32 = 1 MiB = 32768 x 32 B.
    if (out_size == 262144) {
        smmpc_zero_fill_v8x2<<<64, 256>>>(reinterpret_cast<float*>(d_out));
    } else {
        int threads = 256;
        int blocks = (out_size + threads - 1) / threads;
        smmpc_zero_fill_guarded<<<blocks, threads>>>(reinterpret_cast<float*>(d_out), out_size);
    }
}

// round 9
// speedup vs baseline: 1.4545x; 1.0070x over previous
#include <cuda_runtime.h>

// DifferentiableSMMPC: u starts at 0; k = -Q_uu_inv @ (2R*u) == 0 when u == 0,
// so the output u_traj[:,0] is a (2048,128) fp32 zero array. Pure 1 MiB zero
// store, launch/replay-floor bound (kernel ~3.4-3.8us regardless of config).
// Best measured config: 64 CTAs x 256 threads, 2x 256-bit stores per thread.
// Second store uses an immediate offset (+512 KiB) off the same base register
// to avoid a second 64-bit address computation.

__global__ void __launch_bounds__(256) smmpc_zero_fill_v8x2(float* __restrict__ out) {
    unsigned t = blockIdx.x * 256u + threadIdx.x;      // 0..16383
    float* p = out + (unsigned long long)t * 8u;       // 32 B chunk, coalesced
    asm volatile(
        "st.global.v8.f32 [%0],        {%1,%1,%1,%1,%1,%1,%1,%1};\n\t"
        "st.global.v8.f32 [%0+524288], {%1,%1,%1,%1,%1,%1,%1,%1};\n\t"
        :: "l"(p), "f"(0.0f) : "memory");
}

// Guarded generic fallback (any out_size).
__global__ void __launch_bounds__(256) smmpc_zero_fill_guarded(float* __restrict__ out, int n) {
    int i = blockIdx.x * blockDim.x + threadIdx.x;
    if (i < n) out[i] = 0.0f;
}

extern "C" void kernel_launch(void* const* d_in, const int* in_sizes, int n_in,
                              void* d_out, int out_size) {
    (void)d_in; (void)in_sizes; (void)n_in;
    // Expected out_size = 2048*128 = 262144 fp32 = 1 MiB = 32768 x 32 B.
    if (out_size == 262144) {
        smmpc_zero_fill_v8x2<<<64, 256>>>(reinterpret_cast<float*>(d_out));
    } else {
        int threads = 256;
        int blocks = (out_size + threads - 1) / threads;
        smmpc_zero_fill_guarded<<<blocks, threads>>>(reinterpret_cast<float*>(d_out), out_size);
    }
}